// round 16
// baseline (speedup 1.0000x reference)
#include <cuda_runtime.h>
#include <math_constants.h>

// Problem constants (fixed by the reference)
#define B_   32
#define S_   16
#define T_   260
#define D_   768
#define P_   256
#define TOPK 4

#define TOK_N   ((long long)B_ * S_ * T_ * D_)   // 102,236,160
#define MASK_N  (B_ * T_)                        // 8,320
#define IDX_N   (B_ * P_)                        // 8,192
#define OFF_MASK  (TOK_N)
#define OFF_IDX   (OFF_MASK + MASK_N)
#define OFF_VALID (OFF_IDX + IDX_N)
#define OFF_MEAN  (OFF_VALID + IDX_N)

// Copy geometry: 256 thr x 6 float4 = 1536 f4/blk (matches session-best
// per-block footprint). Per batch: 798,720 f4 = 520 blocks exactly.
#define THREADS     256
#define V_PER_THR   6
#define F4_PER_BLK  (THREADS * V_PER_THR)            // 1536
#define BLK_PER_B   520
#define NCOPY       (B_ * BLK_PER_B)                 // 16,640

__device__ int   g_idx[B_ * P_];
__device__ int   g_flag[B_];     // route block b publishes g_idx
__device__ int   g_done[B_];     // copy-block arrival counter (self-reset)
__device__ float g_sum;          // mean accumulator (self-reset)
__device__ int   g_rdone;        // route ticket (self-reset)

// ---------------------------------------------------------------------------
// Routing for one batch (256 threads).
// ---------------------------------------------------------------------------
__device__ __forceinline__ void do_route(int b, const float* __restrict__ z,
                                         float* __restrict__ out) {
    const int p = threadIdx.x;
    const int lane = p & 31;
    const int w    = p >> 5;

    const float* zb = z + (long long)b * S_ * P_;
    float score = -CUDART_INF_F;
    #pragma unroll
    for (int s = 0; s < S_; ++s)
        score = fmaxf(score, zb[s * P_ + p]);

    __shared__ float sval[P_];
    __shared__ int   sorder[P_];
    __shared__ int   wsum[P_ / 32];
    __shared__ float rv[P_];
    __shared__ int   ri[P_];

    sval[p] = score;
    int act = (score > 0.5f) ? 1 : 0;

    unsigned m = __ballot_sync(0xffffffffu, act);
    int wpre = __popc(m & ((lane == 31) ? 0xffffffffu : ((1u << (lane + 1)) - 1u)));
    if (lane == 31) wsum[w] = wpre;
    __syncthreads();
    int off = 0;
    #pragma unroll
    for (int i = 0; i < P_ / 32; ++i) off += (i < w) ? wsum[i] : 0;
    int pre = off + wpre;
    int cnt = 0;
    #pragma unroll
    for (int i = 0; i < P_ / 32; ++i) cnt += wsum[i];

    if (cnt == 0) {
        // fallback: top-4 scores (ties -> lowest index, matching lax.top_k)
        int is_fb = 0;
        #pragma unroll
        for (int k = 0; k < TOPK; ++k) {
            rv[p] = sval[p];
            ri[p] = p;
            __syncthreads();
            #pragma unroll
            for (int o = P_ / 2; o > 0; o >>= 1) {
                if (p < o) {
                    float ov = rv[p + o]; int oi = ri[p + o];
                    if (ov > rv[p] || (ov == rv[p] && oi < ri[p])) { rv[p] = ov; ri[p] = oi; }
                }
                __syncthreads();
            }
            int win = ri[0];
            __syncthreads();
            if (p == win) { is_fb = 1; sval[p] = -CUDART_INF_F; }
            __syncthreads();
        }
        act = is_fb;
        m = __ballot_sync(0xffffffffu, act);
        wpre = __popc(m & ((lane == 31) ? 0xffffffffu : ((1u << (lane + 1)) - 1u)));
        if (lane == 31) wsum[w] = wpre;
        __syncthreads();
        off = 0;
        #pragma unroll
        for (int i = 0; i < P_ / 32; ++i) off += (i < w) ? wsum[i] : 0;
        pre = off + wpre;
        cnt = 0;
        #pragma unroll
        for (int i = 0; i < P_ / 32; ++i) cnt += wsum[i];
    }

    // stable partition: active indices ascending, then inactive ascending
    int rank = act ? (pre - 1) : (cnt + (p - pre));
    sorder[rank] = p;
    __syncthreads();

    int v = (p < cnt) ? 1 : 0;
    int pidx = v ? sorder[p] : 0;

    g_idx[b * P_ + p] = pidx;

    out[OFF_MASK  + (long long)b * T_ + p] = v ? 1.0f : 0.0f;
    if (p < (T_ - P_))
        out[OFF_MASK + (long long)b * T_ + P_ + p] = 1.0f;  // tail always valid
    out[OFF_IDX   + (long long)b * P_ + p] = (float)pidx;
    out[OFF_VALID + (long long)b * P_ + p] = v ? 1.0f : 0.0f;

    __syncthreads();                       // all g_idx[b,*] written
    if (p == 0) {
        __threadfence();
        atomicExch(&g_flag[b], 1);         // publish g_idx for this batch

        // active_mean: exact (sum of small ints), order-independent
        atomicAdd(&g_sum, (float)cnt);
        __threadfence();
        int tk = atomicAdd(&g_rdone, 1);
        if (tk == B_ - 1) {
            __threadfence();
            float t = atomicAdd(&g_sum, 0.0f);
            out[OFF_MEAN] = t / (float)B_;
            atomicExch(&g_sum, 0.0f);      // reset for next replay
            atomicExch(&g_rdone, 0);
        }
    }
}

// ---------------------------------------------------------------------------
// Single fused kernel.
//   blocks 0..31 : routing (wave 1, hidden under the copy)
//   blocks 32..  : flat identity memcpy (NOT gated). The last copy block of
//                  each batch then performs the per-batch fixup for rows
//                  where g_idx[t] != t (expected: none for this input).
// ---------------------------------------------------------------------------
__global__ __launch_bounds__(THREADS)
void fused_kernel(const float* __restrict__ tok, const float* __restrict__ z,
                  float* __restrict__ out) {
    if (blockIdx.x < B_) {
        do_route(blockIdx.x, z, out);
        return;
    }

    const int gb = blockIdx.x - B_;             // 0 .. NCOPY-1
    const int b  = gb / BLK_PER_B;              // batch this block belongs to
    const int tid = threadIdx.x;

    // --- identity copy (no dependency on routing) ---
    const long long base = (long long)gb * F4_PER_BLK + tid;
    const float4* __restrict__ s4 = reinterpret_cast<const float4*>(tok);
    float4* __restrict__ d4 = reinterpret_cast<float4*>(out);

    float4 v[V_PER_THR];
    #pragma unroll
    for (int k = 0; k < V_PER_THR; ++k)
        v[k] = __ldcs(&s4[base + (long long)k * THREADS]);
    #pragma unroll
    for (int k = 0; k < V_PER_THR; ++k)
        __stcs(&d4[base + (long long)k * THREADS], v[k]);

    // --- last copy block of batch b does the fixup inline ---
    __shared__ int is_last;
    if (tid == 0) {
        __threadfence();                        // order our stores before count
        int old = atomicAdd(&g_done[b], 1);
        is_last = (old == BLK_PER_B - 1);
    }
    __syncthreads();
    if (!is_last) return;

    // Wait for route block b (in practice long finished by now).
    if (tid == 0) {
        while (atomicAdd(&g_flag[b], 0) == 0) __nanosleep(32);
    }
    __syncthreads();
    __threadfence();

    __shared__ int list[P_];
    __shared__ int nmis;
    if (tid == 0) nmis = 0;
    __syncthreads();

    if (tid < P_) {
        int idx = __ldcg(&g_idx[b * P_ + tid]);
        if (idx != tid) {
            int k = atomicAdd(&nmis, 1);
            list[k] = tid;
        }
    }
    __syncthreads();

    const int LPR = D_ / 4;                     // 192 float4 per row
    for (int m = 0; m < nmis; ++m) {
        const int t  = list[m];
        const int st = __ldcg(&g_idx[b * P_ + t]);
        for (int i = tid; i < S_ * LPR; i += THREADS) {
            const int s    = i / LPR;
            const int lane = i % LPR;
            const long long bs = (long long)b * S_ + s;
            d4[(bs * T_ + t)  * LPR + lane] = s4[(bs * T_ + st) * LPR + lane];
        }
    }
    __syncthreads();

    if (tid == 0) {                             // reset for next graph replay
        atomicExch(&g_done[b], 0);
        atomicExch(&g_flag[b], 0);
    }
}

// ---------------------------------------------------------------------------
extern "C" void kernel_launch(void* const* d_in, const int* in_sizes, int n_in,
                              void* d_out, int out_size) {
    const float* tokens = (const float*)d_in[0];
    const float* z      = (const float*)d_in[1];
    if (n_in >= 2 && in_sizes[0] == B_ * S_ * P_) {
        tokens = (const float*)d_in[1];
        z      = (const float*)d_in[0];
    }
    float* out = (float*)d_out;

    fused_kernel<<<B_ + NCOPY, THREADS>>>(tokens, z, out);
}

// round 17
// speedup vs baseline: 1.0029x; 1.0029x over previous
#include <cuda_runtime.h>
#include <math_constants.h>

// Problem constants (fixed by the reference)
#define B_   32
#define S_   16
#define T_   260
#define D_   768
#define P_   256
#define TOPK 4

#define TOK_N   ((long long)B_ * S_ * T_ * D_)   // 102,236,160
#define MASK_N  (B_ * T_)                        // 8,320
#define IDX_N   (B_ * P_)                        // 8,192
#define OFF_MASK  (TOK_N)
#define OFF_IDX   (OFF_MASK + MASK_N)
#define OFF_VALID (OFF_IDX + IDX_N)
#define OFF_MEAN  (OFF_VALID + IDX_N)

// Copy geometry: 256 thr x 6 float4 = 1536 f4/blk (matches session-best
// per-block footprint). Per batch: 798,720 f4 = 520 blocks exactly.
#define THREADS     256
#define V_PER_THR   6
#define F4_PER_BLK  (THREADS * V_PER_THR)            // 1536
#define BLK_PER_B   520
#define NCOPY       (B_ * BLK_PER_B)                 // 16,640

__device__ int   g_idx[B_ * P_];
__device__ int   g_flag[B_];     // route block b publishes g_idx
__device__ int   g_done[B_];     // copy-block arrival counter (self-reset)
__device__ float g_sum;          // mean accumulator (self-reset)
__device__ int   g_rdone;        // route ticket (self-reset)

// ---------------------------------------------------------------------------
// Routing for one batch (256 threads).
// ---------------------------------------------------------------------------
__device__ __forceinline__ void do_route(int b, const float* __restrict__ z,
                                         float* __restrict__ out) {
    const int p = threadIdx.x;
    const int lane = p & 31;
    const int w    = p >> 5;

    const float* zb = z + (long long)b * S_ * P_;
    float score = -CUDART_INF_F;
    #pragma unroll
    for (int s = 0; s < S_; ++s)
        score = fmaxf(score, zb[s * P_ + p]);

    __shared__ float sval[P_];
    __shared__ int   sorder[P_];
    __shared__ int   wsum[P_ / 32];
    __shared__ float rv[P_];
    __shared__ int   ri[P_];

    sval[p] = score;
    int act = (score > 0.5f) ? 1 : 0;

    unsigned m = __ballot_sync(0xffffffffu, act);
    int wpre = __popc(m & ((lane == 31) ? 0xffffffffu : ((1u << (lane + 1)) - 1u)));
    if (lane == 31) wsum[w] = wpre;
    __syncthreads();
    int off = 0;
    #pragma unroll
    for (int i = 0; i < P_ / 32; ++i) off += (i < w) ? wsum[i] : 0;
    int pre = off + wpre;
    int cnt = 0;
    #pragma unroll
    for (int i = 0; i < P_ / 32; ++i) cnt += wsum[i];

    if (cnt == 0) {
        // fallback: top-4 scores (ties -> lowest index, matching lax.top_k)
        int is_fb = 0;
        #pragma unroll
        for (int k = 0; k < TOPK; ++k) {
            rv[p] = sval[p];
            ri[p] = p;
            __syncthreads();
            #pragma unroll
            for (int o = P_ / 2; o > 0; o >>= 1) {
                if (p < o) {
                    float ov = rv[p + o]; int oi = ri[p + o];
                    if (ov > rv[p] || (ov == rv[p] && oi < ri[p])) { rv[p] = ov; ri[p] = oi; }
                }
                __syncthreads();
            }
            int win = ri[0];
            __syncthreads();
            if (p == win) { is_fb = 1; sval[p] = -CUDART_INF_F; }
            __syncthreads();
        }
        act = is_fb;
        m = __ballot_sync(0xffffffffu, act);
        wpre = __popc(m & ((lane == 31) ? 0xffffffffu : ((1u << (lane + 1)) - 1u)));
        if (lane == 31) wsum[w] = wpre;
        __syncthreads();
        off = 0;
        #pragma unroll
        for (int i = 0; i < P_ / 32; ++i) off += (i < w) ? wsum[i] : 0;
        pre = off + wpre;
        cnt = 0;
        #pragma unroll
        for (int i = 0; i < P_ / 32; ++i) cnt += wsum[i];
    }

    // stable partition: active indices ascending, then inactive ascending
    int rank = act ? (pre - 1) : (cnt + (p - pre));
    sorder[rank] = p;
    __syncthreads();

    int v = (p < cnt) ? 1 : 0;
    int pidx = v ? sorder[p] : 0;

    g_idx[b * P_ + p] = pidx;

    out[OFF_MASK  + (long long)b * T_ + p] = v ? 1.0f : 0.0f;
    if (p < (T_ - P_))
        out[OFF_MASK + (long long)b * T_ + P_ + p] = 1.0f;  // tail always valid
    out[OFF_IDX   + (long long)b * P_ + p] = (float)pidx;
    out[OFF_VALID + (long long)b * P_ + p] = v ? 1.0f : 0.0f;

    __syncthreads();                       // all g_idx[b,*] written
    if (p == 0) {
        __threadfence();
        atomicExch(&g_flag[b], 1);         // publish g_idx for this batch

        // active_mean: exact (sum of small ints), order-independent
        atomicAdd(&g_sum, (float)cnt);
        __threadfence();
        int tk = atomicAdd(&g_rdone, 1);
        if (tk == B_ - 1) {
            __threadfence();
            float t = atomicAdd(&g_sum, 0.0f);
            out[OFF_MEAN] = t / (float)B_;
            atomicExch(&g_sum, 0.0f);      // reset for next replay
            atomicExch(&g_rdone, 0);
        }
    }
}

// ---------------------------------------------------------------------------
// Single fused kernel.
//   blocks 0..31 : routing (wave 1, hidden under the copy)
//   blocks 32..  : flat identity memcpy (NOT gated). The last copy block of
//                  each batch then performs the per-batch fixup for rows
//                  where g_idx[t] != t (expected: none for this input).
// ---------------------------------------------------------------------------
__global__ __launch_bounds__(THREADS)
void fused_kernel(const float* __restrict__ tok, const float* __restrict__ z,
                  float* __restrict__ out) {
    if (blockIdx.x < B_) {
        do_route(blockIdx.x, z, out);
        return;
    }

    const int gb = blockIdx.x - B_;             // 0 .. NCOPY-1
    const int b  = gb / BLK_PER_B;              // batch this block belongs to
    const int tid = threadIdx.x;

    // --- identity copy (no dependency on routing) ---
    const long long base = (long long)gb * F4_PER_BLK + tid;
    const float4* __restrict__ s4 = reinterpret_cast<const float4*>(tok);
    float4* __restrict__ d4 = reinterpret_cast<float4*>(out);

    float4 v[V_PER_THR];
    #pragma unroll
    for (int k = 0; k < V_PER_THR; ++k)
        v[k] = __ldcs(&s4[base + (long long)k * THREADS]);
    #pragma unroll
    for (int k = 0; k < V_PER_THR; ++k)
        __stcs(&d4[base + (long long)k * THREADS], v[k]);

    // --- last copy block of batch b does the fixup inline ---
    __shared__ int is_last;
    if (tid == 0) {
        __threadfence();                        // order our stores before count
        int old = atomicAdd(&g_done[b], 1);
        is_last = (old == BLK_PER_B - 1);
    }
    __syncthreads();
    if (!is_last) return;

    // Wait for route block b (in practice long finished by now).
    if (tid == 0) {
        while (atomicAdd(&g_flag[b], 0) == 0) __nanosleep(32);
    }
    __syncthreads();
    __threadfence();

    __shared__ int list[P_];
    __shared__ int nmis;
    if (tid == 0) nmis = 0;
    __syncthreads();

    if (tid < P_) {
        int idx = __ldcg(&g_idx[b * P_ + tid]);
        if (idx != tid) {
            int k = atomicAdd(&nmis, 1);
            list[k] = tid;
        }
    }
    __syncthreads();

    const int LPR = D_ / 4;                     // 192 float4 per row
    for (int m = 0; m < nmis; ++m) {
        const int t  = list[m];
        const int st = __ldcg(&g_idx[b * P_ + t]);
        for (int i = tid; i < S_ * LPR; i += THREADS) {
            const int s    = i / LPR;
            const int lane = i % LPR;
            const long long bs = (long long)b * S_ + s;
            d4[(bs * T_ + t)  * LPR + lane] = s4[(bs * T_ + st) * LPR + lane];
        }
    }
    __syncthreads();

    if (tid == 0) {                             // reset for next graph replay
        atomicExch(&g_done[b], 0);
        atomicExch(&g_flag[b], 0);
    }
}

// ---------------------------------------------------------------------------
extern "C" void kernel_launch(void* const* d_in, const int* in_sizes, int n_in,
                              void* d_out, int out_size) {
    const float* tokens = (const float*)d_in[0];
    const float* z      = (const float*)d_in[1];
    if (n_in >= 2 && in_sizes[0] == B_ * S_ * P_) {
        tokens = (const float*)d_in[1];
        z      = (const float*)d_in[0];
    }
    float* out = (float*)d_out;

    fused_kernel<<<B_ + NCOPY, THREADS>>>(tokens, z, out);
}